// round 16
// baseline (speedup 1.0000x reference)
#include <cuda_runtime.h>
#include <cstdint>

// 3D spatial correlation sampler, patch=7, dil=1, k=1, s=1, pad=0
// in1,in2: [B=2, C=32, D=32, H=32, W=32] fp32
// out: [B, 7, 7, 7, D, H, W] fp32
//
// Grid = (b, d, hq, od) -> 1792 blocks; 224 threads = 7 warps, warp = oh.
// ZERO-BARRIER mainloop (R15): all 4 slab chunks cp.async'd in the prologue
// into 4 distinct buffers; per-chunk mbarriers (count 224, async arrive)
// replace all mid-loop __syncthreads. in1 read directly via full-density
// LDG.128 (lane remap hl=lane>>2, wi=lane&3). Inner math: pair-aligned
// fma.rn.f32x2; slab pitch 44 conflict-free.
// NEW (R16): outputs stored with st.global.cs (evict-first) so the 90MB
// write-once stream doesn't evict the 16.8MB L2-resident inputs.

#define BB 2
#define CC 32
#define DD 32
#define HH 32
#define WW 32
#define PP 7
#define TH 8
#define NTHREADS 224
#define CCHUNK 8
#define NCHUNK (CC / CCHUNK)      // 4

#define SLAB_ROWS (TH + 6)                         // 14
#define SLAB_PITCH 44                              // conflict-free under lane map
#define SLABC_SZ (CCHUNK * SLAB_ROWS * SLAB_PITCH) // 4928 floats per buf
#define BAR_FLOATS 16                              // 4 mbarriers + pad
#define SLAB_OFF BAR_FLOATS
#define SMEM_FLOATS (SLAB_OFF + NCHUNK * SLABC_SZ) // 19728 floats = 78912 B

typedef unsigned long long u64;

__device__ __forceinline__ void cp_async16(uint32_t dst, const void* src, int src_bytes) {
    asm volatile("cp.async.cg.shared.global [%0], [%1], 16, %2;\n"
                 :: "r"(dst), "l"(src), "r"(src_bytes));
}
__device__ __forceinline__ void mbar_init(uint32_t addr, uint32_t count) {
    asm volatile("mbarrier.init.shared.b64 [%0], %1;" :: "r"(addr), "r"(count) : "memory");
}
__device__ __forceinline__ void cp_async_arrive(uint32_t addr) {
    asm volatile("cp.async.mbarrier.arrive.noinc.shared.b64 [%0];" :: "r"(addr) : "memory");
}
__device__ __forceinline__ void mbar_wait(uint32_t addr, int phase) {
    asm volatile(
        "{\n\t.reg .pred P;\n\t"
        "WL_%=:\n\t"
        "mbarrier.try_wait.parity.acquire.cta.shared::cta.b64 P, [%0], %1, 0x989680;\n\t"
        "@P bra.uni WD_%=;\n\t"
        "bra.uni WL_%=;\n\t"
        "WD_%=:\n\t}"
        :: "r"(addr), "r"(phase) : "memory");
}
__device__ __forceinline__ void ffma2(u64& acc, u64 a, u64 b) {
    asm("fma.rn.f32x2 %0, %1, %2, %0;" : "+l"(acc) : "l"(a), "l"(b));
}
// O = (hi32(lo_src), lo32(hi_src))
__device__ __forceinline__ u64 mix_hi_lo(u64 lo_src, u64 hi_src) {
    uint32_t a0, a1, b0, b1;
    asm("mov.b64 {%0,%1}, %2;" : "=r"(a0), "=r"(a1) : "l"(lo_src));
    asm("mov.b64 {%0,%1}, %2;" : "=r"(b0), "=r"(b1) : "l"(hi_src));
    u64 r;
    asm("mov.b64 %0, {%1,%2};" : "=l"(r) : "r"(a1), "r"(b0));
    return r;
}
// streaming (evict-first) 16B store of two packed f32x2 accumulators
__device__ __forceinline__ void stcs_pair(float* p, u64 v0, u64 v1) {
    float2 f0, f1;
    asm("mov.b64 {%0,%1}, %2;" : "=f"(f0.x), "=f"(f0.y) : "l"(v0));
    asm("mov.b64 {%0,%1}, %2;" : "=f"(f1.x), "=f"(f1.y) : "l"(v1));
    asm volatile("st.global.cs.v4.f32 [%0], {%1,%2,%3,%4};"
                 :: "l"(p), "f"(f0.x), "f"(f0.y), "f"(f1.x), "f"(f1.y)
                 : "memory");
}

__global__ __launch_bounds__(NTHREADS, 2)
void corr3d_kernel(const float* __restrict__ in1,
                   const float* __restrict__ in2,
                   float* __restrict__ out)
{
    extern __shared__ float sm[];   // [4 mbars | slab buf0..buf3]

    int bx = blockIdx.x;            // ((b*32 + d)*4 + hq)*7 + od
    const int od = bx % 7;   bx /= 7;
    const int hq = bx & 3;   bx >>= 2;
    const int d  = bx & 31;
    const int b  = bx >> 5;
    const int h0 = hq * TH;

    const int t    = threadIdx.x;
    const int lane = t & 31;
    const int oh   = t >> 5;        // warp id = oh
    const int hl   = lane >> 2;     // 0..7 (4 lanes per h-row)
    const int wi   = lane & 3;      // 0..3
    const int w0   = wi * 8;

    const int z = d + od - 3;       // uniform per block
    const bool zvalid = (z >= 0) && (z < DD);

    // acc2[pw][j] packs outputs (w0+2j, w0+2j+1)
    u64 acc2[PP][4];
    #pragma unroll
    for (int pw = 0; pw < PP; pw++)
        #pragma unroll
        for (int j = 0; j < 4; j++) acc2[pw][j] = 0ull;

    if (zvalid) {
        const float* in1g = in1 + ((size_t)(b * CC) * DD + d) * (HH * WW)
                                + (h0 + hl) * WW + w0;
        const float* in2g = in2 + ((size_t)(b * CC) * DD + z) * (HH * WW);
        const uint32_t smem_u32 = (uint32_t)__cvta_generic_to_shared(sm);
        const uint32_t slab0 = smem_u32 + SLAB_OFF * 4u;

        if (t == 0) {
            #pragma unroll
            for (int ch = 0; ch < NCHUNK; ch++)
                mbar_init(smem_u32 + 8u * ch, NTHREADS);
        }
        __syncthreads();   // mbarriers visible before any arrive

        // ---- prologue: stage ALL 4 slab chunks, arrive per chunk ----
        #pragma unroll
        for (int ch = 0; ch < NCHUNK; ch++) {
            const float* g2 = in2g + (size_t)(ch * CCHUNK) * (DD * HH * WW);
            uint32_t slabb = slab0 + (uint32_t)(ch * SLABC_SZ) * 4u;
            #pragma unroll
            for (int i = 0; i < 5; i++) {
                int slot = i * NTHREADS + t;            // 0..1119
                int c    = slot / 140;
                int rem  = slot - c * 140;
                int r    = rem / 10;
                int s4   = rem - r * 10;
                int hg   = h0 + r - 3;
                bool v   = (s4 >= 1) && (s4 <= 8) && (hg >= 0) && (hg < HH);
                const float* src = v ? (g2 + (size_t)c * (DD * HH * WW)
                                           + hg * WW + (s4 - 1) * 4)
                                     : g2;       // clamped dummy, zfilled
                cp_async16(slabb + (uint32_t)(c * (SLAB_ROWS * SLAB_PITCH)
                                              + r * SLAB_PITCH + s4 * 4) * 4u,
                           src, v ? 16 : 0);
            }
            cp_async_arrive(smem_u32 + 8u * ch);   // fires when copies land
        }

        // ---- mainloop: NO __syncthreads; warps proceed independently ----
        for (int ch = 0; ch < NCHUNK; ch++) {
            mbar_wait(smem_u32 + 8u * ch, 0);

            const float* ap = in1g + (size_t)(ch * CCHUNK) * (DD * HH * WW);
            const float* bp = sm + SLAB_OFF + ch * SLABC_SZ
                                 + (hl + oh) * SLAB_PITCH + w0;

            #pragma unroll
            for (int c = 0; c < CCHUNK; c++) {
                ulonglong2 a01 = *(const ulonglong2*)(ap);      // av[0..3]
                ulonglong2 a23 = *(const ulonglong2*)(ap + 4);  // av[4..7]
                ulonglong2 e0  = *(const ulonglong2*)(bp);      // bb[0..3]
                ulonglong2 e1  = *(const ulonglong2*)(bp + 4);  // bb[4..7]
                ulonglong2 e2  = *(const ulonglong2*)(bp + 8);  // bb[8..11]
                ulonglong2 e3  = *(const ulonglong2*)(bp + 12); // bb[12..15]

                u64 A[4] = {a01.x, a01.y, a23.x, a23.y};
                u64 E[8] = {e0.x, e0.y, e1.x, e1.y, e2.x, e2.y, e3.x, e3.y};
                u64 O[7];                       // O[m] = (bb[2m+1], bb[2m+2])
                #pragma unroll
                for (int m = 0; m < 7; m++) O[m] = mix_hi_lo(E[m], E[m + 1]);

                // B pair start k = pw+1+2j; even k -> E[k/2], odd -> O[k/2]
                #pragma unroll
                for (int pw = 0; pw < PP; pw++)
                    #pragma unroll
                    for (int j = 0; j < 4; j++) {
                        const int k = pw + 1 + 2 * j;
                        ffma2(acc2[pw][j], A[j], (k & 1) ? O[k >> 1] : E[k >> 1]);
                    }

                ap += DD * HH * WW;
                bp += SLAB_ROWS * SLAB_PITCH;
            }
        }
    }

    // ---- store (zeros if z OOB), streaming/evict-first ----
    size_t obase = (size_t)(((b * PP + od) * PP + oh) * PP) * (DD * HH * WW)
                 + (size_t)d * (HH * WW) + (h0 + hl) * WW + w0;
    #pragma unroll
    for (int pw = 0; pw < PP; pw++) {
        float* o = out + obase + (size_t)pw * (DD * HH * WW);
        stcs_pair(o,     acc2[pw][0], acc2[pw][1]);
        stcs_pair(o + 4, acc2[pw][2], acc2[pw][3]);
    }
}

extern "C" void kernel_launch(void* const* d_in, const int* in_sizes, int n_in,
                              void* d_out, int out_size)
{
    const float* in1 = (const float*)d_in[0];
    const float* in2 = (const float*)d_in[1];
    float* out = (float*)d_out;

    cudaFuncSetAttribute(corr3d_kernel,
                         cudaFuncAttributeMaxDynamicSharedMemorySize,
                         SMEM_FLOATS * sizeof(float));

    dim3 grid(BB * DD * 4 * PP);   // 1792
    dim3 block(NTHREADS);
    corr3d_kernel<<<grid, block, SMEM_FLOATS * sizeof(float)>>>(in1, in2, out);
}

// round 17
// speedup vs baseline: 1.5130x; 1.5130x over previous
#include <cuda_runtime.h>
#include <cstdint>

// 3D spatial correlation sampler, patch=7, dil=1, k=1, s=1, pad=0
// in1,in2: [B=2, C=32, D=32, H=32, W=32] fp32
// out: [B, 7, 7, 7, D, H, W] fp32
//
// FINAL (R15 config — best measured, 67.7us).
// Grid = (b, d, hq, od) -> 1792 blocks; 224 threads = 7 warps, warp = oh.
// ZERO-BARRIER mainloop: all 4 slab chunks cp.async'd in the prologue into
// 4 distinct buffers (no reuse); per-chunk mbarriers (count 224, async
// arrive) replace every mid-loop __syncthreads, so warps decouple fully.
// in1 is read directly via LDG (lane remap hl=lane>>2/wi=lane&3 makes the
// global reads full-density 128B rows) — no in1 staging at all.
// Inner math: pair-aligned fma.rn.f32x2; slab pitch 44 conflict-free.
// Plain STG.128 stores (st.global.cs measured 1.5x SLOWER on sm_103a).

#define BB 2
#define CC 32
#define DD 32
#define HH 32
#define WW 32
#define PP 7
#define TH 8
#define NTHREADS 224
#define CCHUNK 8
#define NCHUNK (CC / CCHUNK)      // 4

#define SLAB_ROWS (TH + 6)                         // 14
#define SLAB_PITCH 44                              // conflict-free under lane map
#define SLABC_SZ (CCHUNK * SLAB_ROWS * SLAB_PITCH) // 4928 floats per buf
#define BAR_FLOATS 16                              // 4 mbarriers + pad
#define SLAB_OFF BAR_FLOATS
#define SMEM_FLOATS (SLAB_OFF + NCHUNK * SLABC_SZ) // 19728 floats = 78912 B

typedef unsigned long long u64;

__device__ __forceinline__ void cp_async16(uint32_t dst, const void* src, int src_bytes) {
    asm volatile("cp.async.cg.shared.global [%0], [%1], 16, %2;\n"
                 :: "r"(dst), "l"(src), "r"(src_bytes));
}
__device__ __forceinline__ void mbar_init(uint32_t addr, uint32_t count) {
    asm volatile("mbarrier.init.shared.b64 [%0], %1;" :: "r"(addr), "r"(count) : "memory");
}
__device__ __forceinline__ void cp_async_arrive(uint32_t addr) {
    asm volatile("cp.async.mbarrier.arrive.noinc.shared.b64 [%0];" :: "r"(addr) : "memory");
}
__device__ __forceinline__ void mbar_wait(uint32_t addr, int phase) {
    asm volatile(
        "{\n\t.reg .pred P;\n\t"
        "WL_%=:\n\t"
        "mbarrier.try_wait.parity.acquire.cta.shared::cta.b64 P, [%0], %1, 0x989680;\n\t"
        "@P bra.uni WD_%=;\n\t"
        "bra.uni WL_%=;\n\t"
        "WD_%=:\n\t}"
        :: "r"(addr), "r"(phase) : "memory");
}
__device__ __forceinline__ void ffma2(u64& acc, u64 a, u64 b) {
    asm("fma.rn.f32x2 %0, %1, %2, %0;" : "+l"(acc) : "l"(a), "l"(b));
}
// O = (hi32(lo_src), lo32(hi_src))
__device__ __forceinline__ u64 mix_hi_lo(u64 lo_src, u64 hi_src) {
    uint32_t a0, a1, b0, b1;
    asm("mov.b64 {%0,%1}, %2;" : "=r"(a0), "=r"(a1) : "l"(lo_src));
    asm("mov.b64 {%0,%1}, %2;" : "=r"(b0), "=r"(b1) : "l"(hi_src));
    u64 r;
    asm("mov.b64 %0, {%1,%2};" : "=l"(r) : "r"(a1), "r"(b0));
    return r;
}

__global__ __launch_bounds__(NTHREADS, 2)
void corr3d_kernel(const float* __restrict__ in1,
                   const float* __restrict__ in2,
                   float* __restrict__ out)
{
    extern __shared__ float sm[];   // [4 mbars | slab buf0..buf3]

    int bx = blockIdx.x;            // ((b*32 + d)*4 + hq)*7 + od
    const int od = bx % 7;   bx /= 7;
    const int hq = bx & 3;   bx >>= 2;
    const int d  = bx & 31;
    const int b  = bx >> 5;
    const int h0 = hq * TH;

    const int t    = threadIdx.x;
    const int lane = t & 31;
    const int oh   = t >> 5;        // warp id = oh
    const int hl   = lane >> 2;     // 0..7  (4 lanes per h-row)
    const int wi   = lane & 3;      // 0..3
    const int w0   = wi * 8;

    const int z = d + od - 3;       // uniform per block
    const bool zvalid = (z >= 0) && (z < DD);

    // acc2[pw][j] packs outputs (w0+2j, w0+2j+1)
    u64 acc2[PP][4];
    #pragma unroll
    for (int pw = 0; pw < PP; pw++)
        #pragma unroll
        for (int j = 0; j < 4; j++) acc2[pw][j] = 0ull;

    if (zvalid) {
        const float* in1g = in1 + ((size_t)(b * CC) * DD + d) * (HH * WW)
                                + (h0 + hl) * WW + w0;
        const float* in2g = in2 + ((size_t)(b * CC) * DD + z) * (HH * WW);
        const uint32_t smem_u32 = (uint32_t)__cvta_generic_to_shared(sm);
        const uint32_t slab0 = smem_u32 + SLAB_OFF * 4u;

        if (t == 0) {
            #pragma unroll
            for (int ch = 0; ch < NCHUNK; ch++)
                mbar_init(smem_u32 + 8u * ch, NTHREADS);
        }
        __syncthreads();   // mbarriers visible before any arrive

        // ---- prologue: stage ALL 4 slab chunks, arrive per chunk ----
        #pragma unroll
        for (int ch = 0; ch < NCHUNK; ch++) {
            const float* g2 = in2g + (size_t)(ch * CCHUNK) * (DD * HH * WW);
            uint32_t slabb = slab0 + (uint32_t)(ch * SLABC_SZ) * 4u;
            #pragma unroll
            for (int i = 0; i < 5; i++) {
                int slot = i * NTHREADS + t;            // 0..1119
                int c    = slot / 140;
                int rem  = slot - c * 140;
                int r    = rem / 10;
                int s4   = rem - r * 10;
                int hg   = h0 + r - 3;
                bool v   = (s4 >= 1) && (s4 <= 8) && (hg >= 0) && (hg < HH);
                const float* src = v ? (g2 + (size_t)c * (DD * HH * WW)
                                           + hg * WW + (s4 - 1) * 4)
                                     : g2;       // clamped dummy, zfilled
                cp_async16(slabb + (uint32_t)(c * (SLAB_ROWS * SLAB_PITCH)
                                              + r * SLAB_PITCH + s4 * 4) * 4u,
                           src, v ? 16 : 0);
            }
            cp_async_arrive(smem_u32 + 8u * ch);   // fires when copies land
        }

        // ---- mainloop: NO __syncthreads; warps proceed independently ----
        for (int ch = 0; ch < NCHUNK; ch++) {
            mbar_wait(smem_u32 + 8u * ch, 0);

            const float* ap = in1g + (size_t)(ch * CCHUNK) * (DD * HH * WW);
            const float* bp = sm + SLAB_OFF + ch * SLABC_SZ
                                 + (hl + oh) * SLAB_PITCH + w0;

            #pragma unroll
            for (int c = 0; c < CCHUNK; c++) {
                // in1 direct from global (L2-hit; full-density 128B rows)
                ulonglong2 a01 = *(const ulonglong2*)(ap);      // av[0..3]
                ulonglong2 a23 = *(const ulonglong2*)(ap + 4);  // av[4..7]
                ulonglong2 e0  = *(const ulonglong2*)(bp);      // bb[0..3]
                ulonglong2 e1  = *(const ulonglong2*)(bp + 4);  // bb[4..7]
                ulonglong2 e2  = *(const ulonglong2*)(bp + 8);  // bb[8..11]
                ulonglong2 e3  = *(const ulonglong2*)(bp + 12); // bb[12..15]

                u64 A[4] = {a01.x, a01.y, a23.x, a23.y};
                u64 E[8] = {e0.x, e0.y, e1.x, e1.y, e2.x, e2.y, e3.x, e3.y};
                u64 O[7];                       // O[m] = (bb[2m+1], bb[2m+2])
                #pragma unroll
                for (int m = 0; m < 7; m++) O[m] = mix_hi_lo(E[m], E[m + 1]);

                // B pair start k = pw+1+2j; even k -> E[k/2], odd -> O[k/2]
                #pragma unroll
                for (int pw = 0; pw < PP; pw++)
                    #pragma unroll
                    for (int j = 0; j < 4; j++) {
                        const int k = pw + 1 + 2 * j;
                        ffma2(acc2[pw][j], A[j], (k & 1) ? O[k >> 1] : E[k >> 1]);
                    }

                ap += DD * HH * WW;
                bp += SLAB_ROWS * SLAB_PITCH;
            }
        }
    }

    // ---- store (zeros if z OOB); u64 pairs are bit-identical to float2 ----
    size_t obase = (size_t)(((b * PP + od) * PP + oh) * PP) * (DD * HH * WW)
                 + (size_t)d * (HH * WW) + (h0 + hl) * WW + w0;
    #pragma unroll
    for (int pw = 0; pw < PP; pw++) {
        float* o = out + obase + (size_t)pw * (DD * HH * WW);
        *(ulonglong2*)(o)     = make_ulonglong2(acc2[pw][0], acc2[pw][1]);
        *(ulonglong2*)(o + 4) = make_ulonglong2(acc2[pw][2], acc2[pw][3]);
    }
}

extern "C" void kernel_launch(void* const* d_in, const int* in_sizes, int n_in,
                              void* d_out, int out_size)
{
    const float* in1 = (const float*)d_in[0];
    const float* in2 = (const float*)d_in[1];
    float* out = (float*)d_out;

    cudaFuncSetAttribute(corr3d_kernel,
                         cudaFuncAttributeMaxDynamicSharedMemorySize,
                         SMEM_FLOATS * sizeof(float));

    dim3 grid(BB * DD * 4 * PP);   // 1792
    dim3 block(NTHREADS);
    corr3d_kernel<<<grid, block, SMEM_FLOATS * sizeof(float)>>>(in1, in2, out);
}